// round 4
// baseline (speedup 1.0000x reference)
#include <cuda_runtime.h>
#include <math.h>
#include <stdint.h>

#define NP 500000
#define NQ 200000
#define CDIM 64
#define EMAX 1200000

// ------------------------- scratch (static device globals) -------------------------
__device__ float g_hsP[(size_t)NP * CDIM];   // hs for conv src=person
__device__ float g_hsQ[(size_t)NQ * CDIM];   // hs for conv src=product
__device__ float g_hp1[(size_t)NP * CDIM];   // layer-0 person output
__device__ float g_hq1[(size_t)NQ * CDIM];   // layer-0 product output
__device__ float g_alsP[NP], g_aldP[NP], g_denP[NP];
__device__ float g_alsQ[NQ], g_aldQ[NQ], g_denQ[NQ];
__device__ float g_e0[EMAX];                 // ebuf for conv0 (P->Q)
__device__ float g_e1[EMAX];                 // ebuf for conv1 (Q->P)

// ------------------------- f32x2 packed-FMA helpers -------------------------
__device__ __forceinline__ unsigned long long pack2(float lo, float hi) {
    unsigned long long r;
    asm("mov.b64 %0, {%1, %2};" : "=l"(r) : "f"(lo), "f"(hi));
    return r;
}
__device__ __forceinline__ void fma2(unsigned long long& acc, unsigned long long a,
                                     unsigned long long b) {
    asm("fma.rn.f32x2 %0, %1, %2, %0;" : "+l"(acc) : "l"(a), "l"(b));
}
__device__ __forceinline__ float2 unpack2(unsigned long long v) {
    float lo, hi;
    asm("mov.b64 {%0, %1}, %2;" : "=f"(lo), "=f"(hi) : "l"(v));
    return make_float2(lo, hi);
}

// ------------------------- kernels -------------------------

// H = f(X) @ W  (f = ELU if flag), fused:
//   als = H @ avs                          (this conv, X as src)
//   ald = f(X) @ (Wd_other @ avd_other)    (other conv, X as dst) — wvec built per block
// 128 threads/block, 128x64 tile, 8x8 per thread, packed f32x2 FMA mainloop.
template <bool ELU>
__global__ __launch_bounds__(128) void gemm_kernel(
    const float* __restrict__ X, const float* __restrict__ W,
    const float* __restrict__ avs,
    const float* __restrict__ Wd_o, const float* __restrict__ avd_o,
    float* __restrict__ H, float* __restrict__ als, float* __restrict__ ald, int N)
{
    __shared__ float xT[64 * 128];   // [k][row] transposed, 32KB
    __shared__ float ws[64 * 64];    // [k][c], 16KB
    __shared__ float wv[64];         // wvec = Wd_o @ avd_o
    const int tid  = threadIdx.x;
    const int row0 = blockIdx.x * 128;

    // wvec (threads 0..63; Wd_o is 16KB, L2-resident)
    if (tid < 64) {
        float s = 0.f;
        #pragma unroll
        for (int c = 0; c < CDIM; c++) s = fmaf(__ldg(&Wd_o[tid * CDIM + c]), __ldg(&avd_o[c]), s);
        wv[tid] = s;
    }
    // load W (coalesced float4)
    {
        const float4* Wv = (const float4*)W;
        float4* wsv = (float4*)ws;
        #pragma unroll
        for (int i = 0; i < 8; i++) wsv[i * 128 + tid] = Wv[i * 128 + tid];
    }
    // load my row of X (optionally ELU'd), store transposed
    {
        int row = row0 + tid;
        if (row < N) {
            const float4* Xv = (const float4*)(X + (size_t)row * CDIM);
            #pragma unroll
            for (int j = 0; j < 16; j++) {
                float4 v = Xv[j];
                if (ELU) {
                    v.x = (v.x > 0.f) ? v.x : expm1f(v.x);
                    v.y = (v.y > 0.f) ? v.y : expm1f(v.y);
                    v.z = (v.z > 0.f) ? v.z : expm1f(v.z);
                    v.w = (v.w > 0.f) ? v.w : expm1f(v.w);
                }
                xT[(4 * j + 0) * 128 + tid] = v.x;
                xT[(4 * j + 1) * 128 + tid] = v.y;
                xT[(4 * j + 2) * 128 + tid] = v.z;
                xT[(4 * j + 3) * 128 + tid] = v.w;
            }
        } else {
            #pragma unroll
            for (int j = 0; j < 64; j++) xT[j * 128 + tid] = 0.f;
        }
    }
    __syncthreads();

    const int ty = tid >> 3;   // 0..15 -> rows ty*8..+7
    const int tx = tid & 7;    // 0..7  -> cols tx*8..+7
    unsigned long long acc[8][4];
    #pragma unroll
    for (int i = 0; i < 8; i++)
        #pragma unroll
        for (int j = 0; j < 4; j++) acc[i][j] = 0ull;

    #pragma unroll 4
    for (int k = 0; k < 64; k++) {
        float4 a0 = *(const float4*)&xT[k * 128 + ty * 8];
        float4 a1 = *(const float4*)&xT[k * 128 + ty * 8 + 4];
        float4 b0 = *(const float4*)&ws[k * 64 + tx * 8];
        float4 b1 = *(const float4*)&ws[k * 64 + tx * 8 + 4];
        unsigned long long bp[4] = {pack2(b0.x, b0.y), pack2(b0.z, b0.w),
                                    pack2(b1.x, b1.y), pack2(b1.z, b1.w)};
        float a[8] = {a0.x, a0.y, a0.z, a0.w, a1.x, a1.y, a1.z, a1.w};
        #pragma unroll
        for (int i = 0; i < 8; i++) {
            unsigned long long ap = pack2(a[i], a[i]);
            #pragma unroll
            for (int j = 0; j < 4; j++) fma2(acc[i][j], ap, bp[j]);
        }
    }

    // avs pairs for fused al_s
    unsigned long long avp[4];
    {
        float4 av0 = __ldg((const float4*)avs + tx * 2);
        float4 av1 = __ldg((const float4*)avs + tx * 2 + 1);
        avp[0] = pack2(av0.x, av0.y); avp[1] = pack2(av0.z, av0.w);
        avp[2] = pack2(av1.x, av1.y); avp[3] = pack2(av1.z, av1.w);
    }

    #pragma unroll
    for (int i = 0; i < 8; i++) {
        int row = row0 + ty * 8 + i;
        unsigned long long alp = 0ull;
        #pragma unroll
        for (int j = 0; j < 4; j++) fma2(alp, acc[i][j], avp[j]);
        float2 f = unpack2(alp);
        float al = f.x + f.y;
        al += __shfl_down_sync(0xffffffffu, al, 4);
        al += __shfl_down_sync(0xffffffffu, al, 2);
        al += __shfl_down_sync(0xffffffffu, al, 1);
        if (row < N) {
            ulonglong2* Hp = (ulonglong2*)(H + (size_t)row * CDIM + tx * 8);
            Hp[0] = make_ulonglong2(acc[i][0], acc[i][1]);
            Hp[1] = make_ulonglong2(acc[i][2], acc[i][3]);
            if (tx == 0) als[row] = al;
        }
    }

    // ald for my row from the transposed tile; wv broadcast from smem
    {
        float s = 0.f;
        #pragma unroll
        for (int k = 0; k < 64; k++) s = fmaf(xT[k * 128 + tid], wv[k], s);
        int row = row0 + tid;
        if (row < N) ald[row] = s;
    }
}

// out rows <- bias (float4 broadcast) ; den <- 0
__global__ void init_kernel(float4* __restrict__ out, const float* __restrict__ bias,
                            float* __restrict__ den, int Nd) {
    int i = blockIdx.x * blockDim.x + threadIdx.x;
    int total = Nd * 16;
    if (i < total) out[i] = __ldg((const float4*)bias + (i & 15));
    if (i < Nd) den[i] = 0.f;
}

// fused edge pass: ex = exp(leaky_relu(als[src]+ald[dst])); den[dst] += ex
__global__ void edgeAB_kernel(const int* __restrict__ src, const int* __restrict__ dst,
                              const float* __restrict__ als, const float* __restrict__ ald,
                              float* __restrict__ den, float* __restrict__ ebuf, int E) {
    int i = blockIdx.x * blockDim.x + threadIdx.x;
    if (i >= E) return;
    int d = __ldg(&dst[i]);
    float v = __ldg(&als[__ldg(&src[i])]) + __ldg(&ald[d]);
    v = (v >= 0.f) ? v : 0.2f * v;
    float ex = __expf(fminf(v, 80.f));
    ebuf[i] = ex;
    atomicAdd(&den[d], ex);
}

// scatter: out[dst] += (ex/den[dst]) * hs[src] — 8 threads/edge, 2x float4 per thread (MLP=2)
__global__ void edgeC_kernel(const int* __restrict__ src, const int* __restrict__ dst,
                             const float* __restrict__ ebuf, const float* __restrict__ den,
                             const float* __restrict__ hs, float* __restrict__ out, int E) {
    long t = (long)blockIdx.x * blockDim.x + threadIdx.x;
    int e = (int)(t >> 3);
    if (e >= E) return;
    int part = (int)(t & 7) * 2;                 // float4 index: 0,2,...,14
    int s = __ldg(&src[e]);
    int d = __ldg(&dst[e]);
    float alpha = __ldg(&ebuf[e]) / __ldg(&den[d]);
    const float4* hp = (const float4*)(hs + (size_t)s * CDIM);
    float4 h0 = __ldg(hp + part);
    float4 h1 = __ldg(hp + part + 1);
    float4* op = (float4*)(out + (size_t)d * CDIM) + part;
    atomicAdd(op,     make_float4(alpha * h0.x, alpha * h0.y, alpha * h0.z, alpha * h0.w));
    atomicAdd(op + 1, make_float4(alpha * h1.x, alpha * h1.y, alpha * h1.z, alpha * h1.w));
}

// in-place ELU, float4
__global__ void elu4_kernel(float4* __restrict__ p, long n4) {
    long i = (long)blockIdx.x * blockDim.x + threadIdx.x;
    if (i >= n4) return;
    float4 v = p[i];
    v.x = (v.x > 0.f) ? v.x : expm1f(v.x);
    v.y = (v.y > 0.f) ? v.y : expm1f(v.y);
    v.z = (v.z > 0.f) ? v.z : expm1f(v.z);
    v.w = (v.w > 0.f) ? v.w : expm1f(v.w);
    p[i] = v;
}

// ------------------------- host orchestration -------------------------

extern "C" void kernel_launch(void* const* d_in, const int* in_sizes, int n_in,
                              void* d_out, int out_size)
{
    const float* xp   = (const float*)d_in[0];
    const float* xq   = (const float*)d_in[1];
    const int*   pv_s = (const int*)d_in[2];
    const int*   pv_d = (const int*)d_in[3];
    const int*   vp_s = (const int*)d_in[4];
    const int*   vp_d = (const int*)d_in[5];
    const float* Wsrc = (const float*)d_in[6];
    const float* Wdst = (const float*)d_in[7];
    const float* asrc = (const float*)d_in[8];
    const float* adst = (const float*)d_in[9];
    const float* bias = (const float*)d_in[10];
    int E = in_sizes[2];

    float *hsP, *hsQ, *hp1, *hq1, *alsP, *aldP, *denP, *alsQ, *aldQ, *denQ, *e0, *e1;
    cudaGetSymbolAddress((void**)&hsP,  g_hsP);
    cudaGetSymbolAddress((void**)&hsQ,  g_hsQ);
    cudaGetSymbolAddress((void**)&hp1,  g_hp1);
    cudaGetSymbolAddress((void**)&hq1,  g_hq1);
    cudaGetSymbolAddress((void**)&alsP, g_alsP);
    cudaGetSymbolAddress((void**)&aldP, g_aldP);
    cudaGetSymbolAddress((void**)&denP, g_denP);
    cudaGetSymbolAddress((void**)&alsQ, g_alsQ);
    cudaGetSymbolAddress((void**)&aldQ, g_aldQ);
    cudaGetSymbolAddress((void**)&denQ, g_denQ);
    cudaGetSymbolAddress((void**)&e0,   g_e0);
    cudaGetSymbolAddress((void**)&e1,   g_e1);

    float* outp = (float*)d_out;                       // persons  [NP*64]
    float* outq = (float*)d_out + (size_t)NP * CDIM;   // products [NQ*64]

    // side streams + event pool (host resources, created once; no device allocs)
    static cudaStream_t sA = nullptr, sB = nullptr;
    static cudaEvent_t  ev[16];
    if (sA == nullptr) {
        cudaStreamCreateWithFlags(&sA, cudaStreamNonBlocking);
        cudaStreamCreateWithFlags(&sB, cudaStreamNonBlocking);
        for (int i = 0; i < 16; i++) cudaEventCreateWithFlags(&ev[i], cudaEventDisableTiming);
    }
    cudaStream_t s0 = 0;  // origin (harness-captured) stream
    int nev = 0;
    #define REC(st)       (cudaEventRecord(ev[nev], (st)), ev[nev++])
    #define WAIT(st, e_)  cudaStreamWaitEvent((st), (e_), 0)

    const unsigned gP  = (NP + 127) / 128, gQ = (NQ + 127) / 128;
    const unsigned giP = (NP * 16 + 255) / 256, giQ = (NQ * 16 + 255) / 256;
    const unsigned gE  = (E + 255) / 256;
    const unsigned gC  = (unsigned)(((long)E * 8 + 255) / 256);

    // ---------------- layer 0 ----------------
    cudaEvent_t eF = REC(s0);
    WAIT(sA, eF); WAIT(sB, eF);

    // gemmP: hsP=hp@Ws0, alsP (conv0 src), aldP=hp@wvec1 (conv1 dst)
    gemm_kernel<false><<<gP, 128, 0, s0>>>(xp, Wsrc + 0 * 4096, asrc + 0 * 64,
                                           Wdst + 1 * 4096, adst + 1 * 64,
                                           hsP, alsP, aldP, NP);
    cudaEvent_t e_gP0 = REC(s0);
    gemm_kernel<false><<<gQ, 128, 0, sA>>>(xq, Wsrc + 1 * 4096, asrc + 1 * 64,
                                           Wdst + 0 * 4096, adst + 0 * 64,
                                           hsQ, alsQ, aldQ, NQ);
    cudaEvent_t e_gQ0 = REC(sA);
    init_kernel<<<giQ, 256, 0, sB>>>((float4*)hq1, bias + 0 * 64, denQ, NQ);
    cudaEvent_t e_iQ0 = REC(sB);
    init_kernel<<<giP, 256, 0, sB>>>((float4*)hp1, bias + 1 * 64, denP, NP);
    cudaEvent_t e_iP0 = REC(sB);

    // conv0 pipeline on s0 (P->Q)
    WAIT(s0, e_gQ0); WAIT(s0, e_iQ0);
    edgeAB_kernel<<<gE, 256, 0, s0>>>(pv_s, pv_d, alsP, aldQ, denQ, e0, E);
    edgeC_kernel<<<gC, 256, 0, s0>>>(pv_s, pv_d, e0, denQ, hsP, hq1, E);
    cudaEvent_t e_C0a = REC(s0);
    // conv1 pipeline on sA (Q->P)
    WAIT(sA, e_gP0); WAIT(sA, e_iP0);
    edgeAB_kernel<<<gE, 256, 0, sA>>>(vp_s, vp_d, alsQ, aldP, denP, e1, E);
    edgeC_kernel<<<gC, 256, 0, sA>>>(vp_s, vp_d, e1, denP, hsQ, hp1, E);
    cudaEvent_t e_C1a = REC(sA);

    // ---------------- layer 1 ----------------
    WAIT(s0, e_C1a);   // gemmP reads hp1 (edgeC1), overwrites aldP (read by l0.edgeAB1)
    gemm_kernel<true><<<gP, 128, 0, s0>>>(hp1, Wsrc + 2 * 4096, asrc + 2 * 64,
                                          Wdst + 3 * 4096, adst + 3 * 64,
                                          hsP, alsP, aldP, NP);
    cudaEvent_t e_gP1 = REC(s0);
    WAIT(sA, e_C0a);   // gemmQ reads hq1 (edgeC0), overwrites aldQ (read by l0.edgeAB0)
    gemm_kernel<true><<<gQ, 128, 0, sA>>>(hq1, Wsrc + 3 * 4096, asrc + 3 * 64,
                                          Wdst + 2 * 4096, adst + 2 * 64,
                                          hsQ, alsQ, aldQ, NQ);
    cudaEvent_t e_gQ1 = REC(sA);
    WAIT(sB, e_C0a);   // initQ overwrites denQ (read by l0.edgeC0)
    init_kernel<<<giQ, 256, 0, sB>>>((float4*)outq, bias + 2 * 64, denQ, NQ);
    cudaEvent_t e_iQ1 = REC(sB);
    WAIT(sB, e_C1a);   // initP overwrites denP (read by l0.edgeC1)
    init_kernel<<<giP, 256, 0, sB>>>((float4*)outp, bias + 3 * 64, denP, NP);
    cudaEvent_t e_iP1 = REC(sB);

    // conv0 pipeline on s0 (P->Q into outq)
    WAIT(s0, e_gQ1); WAIT(s0, e_iQ1);
    edgeAB_kernel<<<gE, 256, 0, s0>>>(pv_s, pv_d, alsP, aldQ, denQ, e0, E);
    edgeC_kernel<<<gC, 256, 0, s0>>>(pv_s, pv_d, e0, denQ, hsP, outq, E);
    // conv1 pipeline on sA (Q->P into outp)
    WAIT(sA, e_gP1); WAIT(sA, e_iP1);
    edgeAB_kernel<<<gE, 256, 0, sA>>>(vp_s, vp_d, alsQ, aldP, denP, e1, E);
    edgeC_kernel<<<gC, 256, 0, sA>>>(vp_s, vp_d, e1, denP, hsQ, outp, E);
    cudaEvent_t e_C1b = REC(sA);

    // final ELU: Q half immediately (overlaps conv1's edgeC), P half after join
    long n4q = (long)NQ * CDIM / 4, n4p = (long)NP * CDIM / 4;
    elu4_kernel<<<(unsigned)((n4q + 255) / 256), 256, 0, s0>>>((float4*)outq, n4q);
    WAIT(s0, e_C1b);
    elu4_kernel<<<(unsigned)((n4p + 255) / 256), 256, 0, s0>>>((float4*)outp, n4p);

    #undef REC
    #undef WAIT
}